// round 9
// baseline (speedup 1.0000x reference)
#include <cuda_runtime.h>
#include <cuda_bf16.h>
#include <cstdint>
#include <cstddef>

// ---------------------------------------------------------------------------
// TreeLSTM via mma.sync (HMMA) bf16 GEMM, hi/lo split compensation:
//   C = Ahi*Bhi + Alo*Bhi + Ahi*Blo   (fp32 register accumulation)
// R9: LSTM cell fused into GEMM epilogue. Weight rows interleaved per unit
//   (levels: 5n+{i,o,u,f0,f1}, BN=160; leaf: 3n+{i,o,u}, BN=96) so one CTA
//   owns complete units; epilogue stages accs in smem, computes cells, and
//   writes h(hi/lo bf16) + c directly. Removes g_buf (~2.1 GB DRAM traffic)
//   and all separate cell kernels.
// ---------------------------------------------------------------------------

#define B_   256
#define LVS  256
#define H_   512
#define X_   300
#define NN   511
#define TH   1536
#define NC   2560
#define KLF  320            // leaf K padded to multiple of 32

#define BM   128
#define BK   32
#define SPB  80             // smem row stride bytes (40 bf16), ldmatrix-safe
#define OFF_AH 0
#define OFF_AL 10240
#define OFF_BH 20480

// -------------------- static scratch ----------------------------------------
__device__ float         g_c  [(size_t)B_ * NN * H_];
__device__ __nv_bfloat16 g_hh [(size_t)B_ * NN * H_];
__device__ __nv_bfloat16 g_hl [(size_t)B_ * NN * H_];
__device__ __nv_bfloat16 g_xh [(size_t)B_ * LVS * KLF];
__device__ __nv_bfloat16 g_xl [(size_t)B_ * LVS * KLF];
__device__ __nv_bfloat16 g_wch[(size_t)NC * 1024];   // interleaved 5n+comp
__device__ __nv_bfloat16 g_wcl[(size_t)NC * 1024];
__device__ __nv_bfloat16 g_wlh[(size_t)TH * KLF];    // interleaved 3n+comp
__device__ __nv_bfloat16 g_wll[(size_t)TH * KLF];
__device__ float         g_bc [NC];                  // interleaved bias (levels)
__device__ float         g_bl [TH];                  // interleaved bias (leaf)

// -------------------- PTX helpers -------------------------------------------
__device__ __forceinline__ uint32_t smem_u32(const void* p) {
    uint32_t a;
    asm("{ .reg .u64 t; cvta.to.shared.u64 t, %1; cvt.u32.u64 %0, t; }"
        : "=r"(a) : "l"(p));
    return a;
}
__device__ __forceinline__ void cp16(uint32_t dst, const void* src) {
    asm volatile("cp.async.cg.shared.global [%0], [%1], 16;" :: "r"(dst), "l"(src));
}
__device__ __forceinline__ void cp_commit() {
    asm volatile("cp.async.commit_group;" ::: "memory");
}
template <int N> __device__ __forceinline__ void cp_wait() {
    asm volatile("cp.async.wait_group %0;" :: "n"(N) : "memory");
}
__device__ __forceinline__ void ldmat4(uint32_t* r, uint32_t addr) {
    asm volatile("ldmatrix.sync.aligned.m8n8.x4.shared.b16 {%0,%1,%2,%3}, [%4];"
                 : "=r"(r[0]), "=r"(r[1]), "=r"(r[2]), "=r"(r[3]) : "r"(addr));
}
__device__ __forceinline__ void mma16816(float* c, const uint32_t* a,
                                         uint32_t b0, uint32_t b1) {
    asm volatile(
        "mma.sync.aligned.m16n8k16.row.col.f32.bf16.bf16.f32 "
        "{%0,%1,%2,%3}, {%4,%5,%6,%7}, {%8,%9}, {%0,%1,%2,%3};"
        : "+f"(c[0]), "+f"(c[1]), "+f"(c[2]), "+f"(c[3])
        : "r"(a[0]), "r"(a[1]), "r"(a[2]), "r"(a[3]), "r"(b0), "r"(b1));
}
__device__ __forceinline__ float sigf(float x) { return 1.0f / (1.0f + expf(-x)); }

// -------------------- fused HMMA GEMM + cell --------------------------------
// GN=5 (levels, HAS_CF): B rows interleaved [i,o,u,f0,f1] per unit, BN=160.
// GN=3 (leaf):           B rows interleaved [i,o,u] per unit,       BN=96.
// A rows: tree_lm>=0 -> contiguous h_cat of node (b=R>>tree_lm, j=R&mask)
//         at level offset off_prev; tree_lm<0 -> row-major stride Kel.
// Epilogue: stage accs to smem, compute cells, write g_hh/g_hl/g_c at
//           node (b = R>>lm, j = R&mask) -> b*NN + off + j.
template <int GN, bool HAS_CF>
__global__ void __launch_bounds__(256) gemm_fused_kernel(
    const __nv_bfloat16* __restrict__ Ah, const __nv_bfloat16* __restrict__ Al,
    const __nv_bfloat16* __restrict__ Bh, const __nv_bfloat16* __restrict__ Bl,
    const float* __restrict__ bias,
    int Kel, int nk, int tree_lm, int lm, int off, int off_prev)
{
    constexpr int BN    = 32 * GN;
    constexpr int NJ    = 2 * GN;
    constexpr int OFF_BL_ = OFF_BH + 80 * BN;
    constexpr int STAGE = OFF_BH + 160 * BN;
    constexpr int NCP   = (1024 + 8 * BN) / 256;
    constexpr int SST   = (GN == 5) ? 164 : 100;   // staging stride (floats)

    extern __shared__ char smem[];
    const uint32_t sbase = smem_u32(smem);
    const int t = threadIdx.x;
    const int lane = t & 31, wid = t >> 5;
    const int m0 = blockIdx.y * BM, n0 = blockIdx.x * BN;

    // ---------- loader setup: NCP slots of 16B per thread ----------
    const char* gp[NCP];
    uint32_t sp[NCP];
    {
        const int msk = (tree_lm >= 0) ? ((1 << tree_lm) - 1) : 0;
#pragma unroll
        for (int i = 0; i < NCP; i++) {
            const int s = t + 256 * i;
            int row, base_s, region;
            if (s < 512)                { region = 0; row = s >> 2;        base_s = OFF_AH; }
            else if (s < 1024)          { region = 1; row = (s - 512) >> 2; base_s = OFF_AL; }
            else if (s < 1024 + 4 * BN) { region = 2; row = (s - 1024) >> 2; base_s = OFF_BH; }
            else            { region = 3; row = (s - 1024 - 4 * BN) >> 2; base_s = OFF_BL_; }
            const int seg = s & 3;
            sp[i] = (uint32_t)base_s + (uint32_t)row * SPB + (uint32_t)seg * 16;
            const __nv_bfloat16* src;
            size_t rb;
            if (region <= 1) {
                const int gr = m0 + row;
                if (tree_lm >= 0)
                    rb = ((size_t)(gr >> tree_lm) * NN + off_prev + 2 * (gr & msk)) * H_;
                else
                    rb = (size_t)gr * Kel;
                src = (region == 0) ? Ah : Al;
            } else {
                rb = (size_t)(n0 + row) * Kel;
                src = (region == 2) ? Bh : Bl;
            }
            gp[i] = (const char*)(src + rb) + seg * 16;
        }
    }

#define LOADS(kk, st) do {                                                    \
        const uint32_t sb_ = sbase + (uint32_t)(st) * STAGE;                  \
        const size_t gb_ = (size_t)(kk) * 64;                                 \
        _Pragma("unroll")                                                     \
        for (int i = 0; i < NCP; i++) cp16(sb_ + sp[i], gp[i] + gb_);         \
        cp_commit();                                                          \
    } while (0)

    // ---------- compute setup: 4x2 warp grid, 32 x (BN/2) warp tile ---------
    const int warp_m = (wid & 3) * 32, warp_n = (wid >> 2) * (BN / 2);
    const uint32_t aoff = (uint32_t)(warp_m + (lane & 15)) * SPB
                        + ((uint32_t)(lane >> 4) << 4);
    const uint32_t boff = (uint32_t)(warp_n + (lane & 15)) * SPB
                        + ((uint32_t)(lane >> 4) << 4);

    float acc[2][NJ][4];
#pragma unroll
    for (int mi = 0; mi < 2; mi++)
#pragma unroll
        for (int nj = 0; nj < NJ; nj++)
#pragma unroll
            for (int q = 0; q < 4; q++) acc[mi][nj][q] = 0.0f;

    LOADS(0, 0);
    LOADS(1, 1);

    for (int k = 0; k < nk; k++) {
        if (k + 1 < nk) cp_wait<1>();
        else            cp_wait<0>();
        __syncthreads();

        const uint32_t sb = sbase + (uint32_t)(k & 1) * STAGE;
#pragma unroll
        for (int ks = 0; ks < 2; ks++) {
            uint32_t ah[2][4], al[2][4];
#pragma unroll
            for (int mi = 0; mi < 2; mi++) {
                const uint32_t o = aoff + (uint32_t)mi * (16 * SPB) + ks * 32;
                ldmat4(ah[mi], sb + OFF_AH + o);
                ldmat4(al[mi], sb + OFF_AL + o);
            }
#pragma unroll
            for (int g = 0; g < GN; g++) {
                uint32_t bh[4], bl[4];
                const uint32_t o = boff + (uint32_t)g * (16 * SPB) + ks * 32;
                ldmat4(bh, sb + OFF_BH + o);
                ldmat4(bl, sb + OFF_BL_ + o);
#pragma unroll
                for (int mi = 0; mi < 2; mi++) {
                    mma16816(acc[mi][2 * g],     ah[mi], bh[0], bh[2]);
                    mma16816(acc[mi][2 * g + 1], ah[mi], bh[1], bh[3]);
                }
#pragma unroll
                for (int mi = 0; mi < 2; mi++) {
                    mma16816(acc[mi][2 * g],     al[mi], bh[0], bh[2]);
                    mma16816(acc[mi][2 * g + 1], al[mi], bh[1], bh[3]);
                }
#pragma unroll
                for (int mi = 0; mi < 2; mi++) {
                    mma16816(acc[mi][2 * g],     ah[mi], bl[0], bl[2]);
                    mma16816(acc[mi][2 * g + 1], ah[mi], bl[1], bl[3]);
                }
            }
        }
        __syncthreads();
        if (k + 2 < nk) LOADS(k + 2, k & 1);
    }
    // loop ended with __syncthreads: all warps done with pipeline smem.

    // ---------- epilogue: stage accs, then fused cell ----------
    float* T = (float*)smem;
    const int er = lane >> 2, ec = (lane & 3) * 2;
#pragma unroll
    for (int mi = 0; mi < 2; mi++) {
        const int r0 = warp_m + mi * 16 + er;
#pragma unroll
        for (int nj = 0; nj < NJ; nj++) {
            const int col = warp_n + nj * 8 + ec;
            float2 v0 = make_float2(acc[mi][nj][0], acc[mi][nj][1]);
            float2 v1 = make_float2(acc[mi][nj][2], acc[mi][nj][3]);
            *(float2*)&T[(size_t)r0 * SST + col] = v0;
            *(float2*)&T[(size_t)(r0 + 8) * SST + col] = v1;
        }
    }
    __syncthreads();

    const int nl = t & 31;
    const int n = blockIdx.x * 32 + nl;      // global h-unit
    float bb[GN];
#pragma unroll
    for (int c = 0; c < GN; c++) bb[c] = bias[n0 + GN * nl + c];
    const int lmsk = (1 << lm) - 1;
#pragma unroll 4
    for (int ii = 0; ii < 16; ii++) {
        const int r = (t >> 5) + 8 * ii;
        const int R = m0 + r;
        const int b = R >> lm, j = R & lmsk;
        const float* Tr = T + (size_t)r * SST + GN * nl;
        const float i_ = Tr[0] + bb[0];
        const float o_ = Tr[1] + bb[1];
        const float u_ = Tr[2] + bb[2];
        float cf = 0.0f;
        if (HAS_CF) {
            const size_t cbase = ((size_t)b * NN + off_prev + 2 * j) * H_ + n;
            cf = sigf(Tr[3] + bb[3]) * g_c[cbase]
               + sigf(Tr[4] + bb[4]) * g_c[cbase + H_];
        }
        const float cn = sigf(i_) * tanhf(u_) + cf;
        const float hn = sigf(o_) * tanhf(cn);
        const size_t ob = ((size_t)b * NN + off + j) * H_ + n;
        g_c[ob] = cn;
        const __nv_bfloat16 hi = __float2bfloat16(hn);
        g_hh[ob] = hi;
        g_hl[ob] = __float2bfloat16(hn - __bfloat162float(hi));
    }
#undef LOADS
}

// -------------------- classifier --------------------------------------------
__global__ void classify_kernel(const float* __restrict__ lw,
                                const float* __restrict__ lb,
                                float* __restrict__ out)
{
    const int node = blockIdx.x * blockDim.x + threadIdx.x;
    if (node >= B_ * NN) return;
    const __nv_bfloat162* hh = (const __nv_bfloat162*)(g_hh + (size_t)node * H_);
    const __nv_bfloat162* hl = (const __nv_bfloat162*)(g_hl + (size_t)node * H_);
    float acc[5] = {0.f, 0.f, 0.f, 0.f, 0.f};
#pragma unroll 4
    for (int k2 = 0; k2 < 256; k2++) {
        const float2 a = __bfloat1622float2(hh[k2]);
        const float2 b = __bfloat1622float2(hl[k2]);
        const float h0 = a.x + b.x, h1 = a.y + b.y;
#pragma unroll
        for (int c = 0; c < 5; c++)
            acc[c] += h0 * lw[c * H_ + 2 * k2] + h1 * lw[c * H_ + 2 * k2 + 1];
    }
#pragma unroll
    for (int c = 0; c < 5; c++)
        out[(size_t)node * 5 + c] = acc[c] + lb[c];
}

// -------------------- packing / gather --------------------------------------
__device__ __forceinline__ void split_bf16(float v, __nv_bfloat16* hi,
                                           __nv_bfloat16* lo, size_t i) {
    const __nv_bfloat16 h = __float2bfloat16(v);
    hi[i] = h;
    lo[i] = __float2bfloat16(v - __bfloat162float(h));
}

// interleaved: row p = 5n+comp; comp {0,1,2}->Uiou rows {n,512+n,1024+n},
//              comp {3,4}->Uf rows {n, 512+n}
__global__ void pack_wcat_kernel(const float* __restrict__ Uiou,
                                 const float* __restrict__ Uf)
{
    const int idx = blockIdx.x * blockDim.x + threadIdx.x;
    if (idx >= NC * 1024) return;
    const int p = idx >> 10, k = idx & 1023;
    const int unit = p / 5, comp = p - 5 * unit;
    const float v = (comp < 3) ? Uiou[(size_t)(comp * 512 + unit) * 1024 + k]
                               : Uf[(size_t)((comp - 3) * 512 + unit) * 1024 + k];
    split_bf16(v, g_wch, g_wcl, idx);
}

__global__ void pack_bias_kernel(const float* __restrict__ bi,
                                 const float* __restrict__ bf)
{
    const int p = blockIdx.x * blockDim.x + threadIdx.x;
    if (p >= NC) return;
    const int unit = p / 5, comp = p - 5 * unit;
    g_bc[p] = (comp < 3) ? bi[comp * 512 + unit] : bf[(comp - 3) * 512 + unit];
}

// leaf interleaved: row p = 3n+comp -> W_iou row comp*512+unit
__global__ void pack_wleaf_kernel(const float* __restrict__ W,
                                  const float* __restrict__ Wb)
{
    const int idx = blockIdx.x * blockDim.x + threadIdx.x;
    if (idx >= TH * KLF) return;
    const int p = idx / KLF, k = idx - p * KLF;
    const int unit = p / 3, comp = p - 3 * unit;
    const int srow = comp * 512 + unit;
    const float v = (k < X_) ? W[(size_t)srow * X_ + k] : 0.0f;
    split_bf16(v, g_wlh, g_wll, idx);
    if (k == 0) g_bl[p] = Wb[srow];
}

__global__ void gather_x_kernel(const int* __restrict__ wid,
                                const float* __restrict__ emb)
{
    const int r = blockIdx.x;
    const int c = threadIdx.x;
    if (c >= KLF) return;
    const float v = (c < X_) ? emb[(size_t)wid[r] * X_ + c] : 0.0f;
    split_bf16(v, g_xh, g_xl, (size_t)r * KLF + c);
}

// -------------------- launch ------------------------------------------------
extern "C" void kernel_launch(void* const* d_in, const int* in_sizes, int n_in,
                              void* d_out, int out_size)
{
    const int*   wordid  = (const int*)  d_in[0];
    const float* emb     = (const float*)d_in[1];
    const float* W_iou_w = (const float*)d_in[2];
    const float* W_iou_b = (const float*)d_in[3];
    const float* U_iou_w = (const float*)d_in[4];
    const float* U_iou_b = (const float*)d_in[5];
    const float* U_f_w   = (const float*)d_in[6];
    const float* U_f_b   = (const float*)d_in[7];
    const float* lin_w   = (const float*)d_in[8];
    const float* lin_b   = (const float*)d_in[9];
    float* out = (float*)d_out;
    (void)in_sizes; (void)n_in; (void)out_size;

    float *pbc, *pbl;
    __nv_bfloat16 *phh, *phl, *pxh, *pxl, *pwch, *pwcl, *pwlh, *pwll;
    cudaGetSymbolAddress((void**)&pbc,  g_bc);
    cudaGetSymbolAddress((void**)&pbl,  g_bl);
    cudaGetSymbolAddress((void**)&phh,  g_hh);
    cudaGetSymbolAddress((void**)&phl,  g_hl);
    cudaGetSymbolAddress((void**)&pxh,  g_xh);
    cudaGetSymbolAddress((void**)&pxl,  g_xl);
    cudaGetSymbolAddress((void**)&pwch, g_wch);
    cudaGetSymbolAddress((void**)&pwcl, g_wcl);
    cudaGetSymbolAddress((void**)&pwlh, g_wlh);
    cudaGetSymbolAddress((void**)&pwll, g_wll);

    // smem: 2 pipeline stages; stage = OFF_BH + 160*BN
    const int smem5 = 2 * (OFF_BH + 160 * 160);   // 92160
    const int smem3 = 2 * (OFF_BH + 160 * 96);    // 71680
    cudaFuncSetAttribute(gemm_fused_kernel<5, true>,
                         cudaFuncAttributeMaxDynamicSharedMemorySize, smem5);
    cudaFuncSetAttribute(gemm_fused_kernel<3, false>,
                         cudaFuncAttributeMaxDynamicSharedMemorySize, smem3);

    // ---- prep ----
    pack_wcat_kernel <<<(NC * 1024 + 255) / 256, 256>>>(U_iou_w, U_f_w);
    pack_bias_kernel <<<(NC + 255) / 256, 256>>>(U_iou_b, U_f_b);
    pack_wleaf_kernel<<<(TH * KLF + 255) / 256, 256>>>(W_iou_w, W_iou_b);
    gather_x_kernel  <<<B_ * LVS, KLF>>>(wordid, emb);

    // ---- leaves: fused GEMM + cell (c_f = 0) ----
    {
        dim3 g(TH / 96, (B_ * LVS) / BM);   // 16 x 512
        gemm_fused_kernel<3, false><<<g, 256, smem3>>>(
            pxh, pxl, pwlh, pwll, pbl, KLF, KLF / BK, -1, 8, 0, 0);
    }

    // ---- internal levels: fused GEMM + cell ----
    static const int offs[10] = {0, 256, 384, 448, 480, 496, 504, 508, 510, 511};
    for (int l = 1; l <= 8; l++) {
        const int m = LVS >> l;
        const int M = B_ * m;
        const int lm = 8 - l;
        dim3 g(NC / 160, M / BM);           // 16 x (M/128)
        gemm_fused_kernel<5, true><<<g, 256, smem5>>>(
            phh, phl, pwch, pwcl, pbc, 1024, 1024 / BK,
            lm, lm, offs[l], offs[l - 1]);
    }

    // ---- classifier ----
    classify_kernel<<<(B_ * NN + 127) / 128, 128>>>(lin_w, lin_b, out);
}

// round 10
// speedup vs baseline: 1.1325x; 1.1325x over previous
#include <cuda_runtime.h>
#include <cuda_bf16.h>
#include <cstdint>
#include <cstddef>

// ---------------------------------------------------------------------------
// TreeLSTM via mma.sync (HMMA) bf16 GEMM, hi/lo split compensation:
//   C = Ahi*Bhi + Alo*Bhi + Ahi*Blo   (fp32 register accumulation)
// R10: attack the LDGSTS issue bottleneck. Weights (and leaf x) stored
//   K-chunked + gmem-pre-swizzled so each CTA chunk tile is ONE contiguous
//   8KB block -> loaded with cp.async.bulk (mbarrier complete_tx) instead of
//   512 x 16B cp.async. Levels keep LDGSTS for A only (1024 ops vs 2048).
//   Swizzle g' = (g + ((row>>1)&3))&3 keeps ldmatrix conflict-free at 64B
//   row stride. Cells/packs reverted to proven R8 structure.
// ---------------------------------------------------------------------------

#define B_   256
#define LVS  256
#define H_   512
#define X_   300
#define NN   511
#define TH   1536
#define NC   2560
#define KLF  320            // leaf K padded to multiple of 32

#define BM   128
#define BN   128
#define BK   32
// per-stage smem: 4 planes of 8KB (Ah, Al, Bh, Bl), 64B rows, swizzled
#define OFF_AH 0
#define OFF_AL 8192
#define OFF_BH 16384
#define OFF_BL 24576
#define STAGE  32768
#define SMEM_BYTES (2 * STAGE)   // 65536 -> 2+ CTAs/SM

// gmem chunk-plane strides (bytes)
#define PLANE_WC  ((long)NC * 64)        // 163840
#define PLANE_WL  ((long)TH * 64)        // 98304
#define PLANE_X   ((long)B_ * LVS * 64)  // 4194304

// -------------------- static scratch ----------------------------------------
__device__ float         g_c  [(size_t)B_ * NN * H_];
__device__ float         g_buf[(size_t)B_ * LVS * TH];
__device__ __nv_bfloat16 g_hh [(size_t)B_ * NN * H_];
__device__ __nv_bfloat16 g_hl [(size_t)B_ * NN * H_];
__device__ __nv_bfloat16 g_xh [(size_t)B_ * LVS * KLF];   // chunked+swizzled
__device__ __nv_bfloat16 g_xl [(size_t)B_ * LVS * KLF];
__device__ __nv_bfloat16 g_wch[(size_t)NC * 1024];        // chunked+swizzled
__device__ __nv_bfloat16 g_wcl[(size_t)NC * 1024];
__device__ __nv_bfloat16 g_wlh[(size_t)TH * KLF];         // chunked+swizzled
__device__ __nv_bfloat16 g_wll[(size_t)TH * KLF];
__device__ float         g_bc [NC];

// -------------------- PTX helpers -------------------------------------------
__device__ __forceinline__ uint32_t smem_u32(const void* p) {
    uint32_t a;
    asm("{ .reg .u64 t; cvta.to.shared.u64 t, %1; cvt.u32.u64 %0, t; }"
        : "=r"(a) : "l"(p));
    return a;
}
__device__ __forceinline__ void cp16(uint32_t dst, const void* src) {
    asm volatile("cp.async.cg.shared.global [%0], [%1], 16;" :: "r"(dst), "l"(src));
}
__device__ __forceinline__ void cp_commit() {
    asm volatile("cp.async.commit_group;" ::: "memory");
}
template <int N> __device__ __forceinline__ void cp_wait() {
    asm volatile("cp.async.wait_group %0;" :: "n"(N) : "memory");
}
__device__ __forceinline__ void bulk_cp(uint32_t dst, const void* src,
                                        uint32_t bytes, uint32_t mbar) {
    asm volatile(
        "cp.async.bulk.shared::cta.global.mbarrier::complete_tx::bytes "
        "[%0], [%1], %2, [%3];"
        :: "r"(dst), "l"(src), "r"(bytes), "r"(mbar) : "memory");
}
__device__ __forceinline__ void mbar_init(uint32_t a, uint32_t cnt) {
    asm volatile("mbarrier.init.shared.b64 [%0], %1;" :: "r"(a), "r"(cnt) : "memory");
}
__device__ __forceinline__ void mbar_expect(uint32_t a, uint32_t bytes) {
    asm volatile("mbarrier.arrive.expect_tx.shared.b64 _, [%0], %1;"
                 :: "r"(a), "r"(bytes) : "memory");
}
__device__ __forceinline__ void mbar_wait(uint32_t a, uint32_t parity) {
    asm volatile(
        "{\n\t.reg .pred P;\n\t"
        "W_%=:\n\t"
        "mbarrier.try_wait.parity.acquire.cta.shared::cta.b64 P, [%0], %1, 0x989680;\n\t"
        "@P bra.uni D_%=;\n\t"
        "bra.uni W_%=;\n\t"
        "D_%=:\n\t}"
        :: "r"(a), "r"(parity) : "memory");
}
__device__ __forceinline__ void fence_async() {
    asm volatile("fence.proxy.async.shared::cta;" ::: "memory");
}
__device__ __forceinline__ void ldmat4(uint32_t* r, uint32_t addr) {
    asm volatile("ldmatrix.sync.aligned.m8n8.x4.shared.b16 {%0,%1,%2,%3}, [%4];"
                 : "=r"(r[0]), "=r"(r[1]), "=r"(r[2]), "=r"(r[3]) : "r"(addr));
}
__device__ __forceinline__ void mma16816(float* c, const uint32_t* a,
                                         uint32_t b0, uint32_t b1) {
    asm volatile(
        "mma.sync.aligned.m16n8k16.row.col.f32.bf16.bf16.f32 "
        "{%0,%1,%2,%3}, {%4,%5,%6,%7}, {%8,%9}, {%0,%1,%2,%3};"
        : "+f"(c[0]), "+f"(c[1]), "+f"(c[2]), "+f"(c[3])
        : "r"(a[0]), "r"(a[1]), "r"(a[2]), "r"(a[3]), "r"(b0), "r"(b1));
}

// swizzled granule offset within a 64B row: g in 0..3, row r
__device__ __host__ __forceinline__ uint32_t swz(uint32_t g, uint32_t r) {
    return ((g + ((r >> 1) & 3)) & 3) << 4;
}

// -------------------- HMMA GEMM ---------------------------------------------
// ABULK=true : A also chunk-contiguous in gmem (leaf) -> 4 bulk copies/chunk.
// ABULK=false: A = h_cat rows (tree mapping), loaded via LDGSTS.
template <bool ABULK>
__global__ void __launch_bounds__(256, 2) gemm_mma_kernel(
    const __nv_bfloat16* __restrict__ Ah, const __nv_bfloat16* __restrict__ Al,
    const __nv_bfloat16* __restrict__ Bh, const __nv_bfloat16* __restrict__ Bl,
    const float* __restrict__ bias, float* __restrict__ C,
    int Ntot, long planeB, long planeA, int nk, int tree_lm, int off_prev)
{
    __shared__ uint64_t mbars[2];
    extern __shared__ char smem[];
    const uint32_t sbase = smem_u32(smem);
    const uint32_t mb0 = smem_u32(&mbars[0]);
    const uint32_t mb1 = smem_u32(&mbars[1]);
    const int t = threadIdx.x;
    const int lane = t & 31, wid = t >> 5;
    const int m0 = blockIdx.y * BM, n0 = blockIdx.x * BN;

    if (t == 0) {
        mbar_init(mb0, 1);
        mbar_init(mb1, 1);
        fence_async();
    }
    __syncthreads();

    // ---------- A loader setup (levels only): rows t>>2 and +64, seg t&3 ----
    const char *pAh0 = nullptr, *pAh1 = nullptr, *pAl0 = nullptr, *pAl1 = nullptr;
    uint32_t dA0 = 0, dA1 = 0;
    if (!ABULK) {
        const int row0 = t >> 2, row1 = row0 + 64;
        const int seg = t & 3;
        const int msk = (1 << tree_lm) - 1;
        const int gr0 = m0 + row0, gr1 = m0 + row1;
        const size_t a0b =
            ((size_t)(gr0 >> tree_lm) * NN + off_prev + 2 * (gr0 & msk)) * H_;
        const size_t a1b =
            ((size_t)(gr1 >> tree_lm) * NN + off_prev + 2 * (gr1 & msk)) * H_;
        pAh0 = (const char*)(Ah + a0b) + seg * 16;
        pAh1 = (const char*)(Ah + a1b) + seg * 16;
        pAl0 = (const char*)(Al + a0b) + seg * 16;
        pAl1 = (const char*)(Al + a1b) + seg * 16;
        dA0 = (uint32_t)row0 * 64 + swz(seg, row0);
        dA1 = (uint32_t)row1 * 64 + swz(seg, row1);
    }

#define LOADS(kk, st, mbar) do {                                              \
        const uint32_t sb_ = sbase + (uint32_t)(st) * STAGE;                  \
        if (!ABULK) {                                                         \
            const size_t gb_ = (size_t)(kk) * 64;                             \
            cp16(sb_ + OFF_AH + dA0, pAh0 + gb_);                             \
            cp16(sb_ + OFF_AH + dA1, pAh1 + gb_);                             \
            cp16(sb_ + OFF_AL + dA0, pAl0 + gb_);                             \
            cp16(sb_ + OFF_AL + dA1, pAl1 + gb_);                             \
            cp_commit();                                                      \
        }                                                                     \
        if (t == 0) {                                                         \
            mbar_expect((mbar), ABULK ? 32768u : 16384u);                     \
            const long bo_ = (long)(kk) * planeB + (long)n0 * 64;             \
            bulk_cp(sb_ + OFF_BH, (const char*)Bh + bo_, 8192, (mbar));       \
            bulk_cp(sb_ + OFF_BL, (const char*)Bl + bo_, 8192, (mbar));       \
            if (ABULK) {                                                      \
                const long ao_ = (long)(kk) * planeA + (long)m0 * 64;         \
                bulk_cp(sb_ + OFF_AH, (const char*)Ah + ao_, 8192, (mbar));   \
                bulk_cp(sb_ + OFF_AL, (const char*)Al + ao_, 8192, (mbar));   \
            }                                                                 \
        }                                                                     \
    } while (0)

    // ---------- compute setup: 4x2 warp grid, 32x64 warp tile ----------
    const int warp_m = (wid & 3) * 32, warp_n = (wid >> 2) * 64;
    const uint32_t half = (uint32_t)(lane >> 4);
    uint32_t aRow[2], aSw[2], bRow[4], bSw[4];
#pragma unroll
    for (int mi = 0; mi < 2; mi++) {
        const uint32_t R = (uint32_t)(warp_m + mi * 16 + (lane & 15));
        aRow[mi] = R * 64;
        aSw[mi] = (R >> 1) & 3;
    }
#pragma unroll
    for (int g = 0; g < 4; g++) {
        const uint32_t R = (uint32_t)(warp_n + g * 16 + (lane & 15));
        bRow[g] = R * 64;
        bSw[g] = (R >> 1) & 3;
    }

    float acc[2][8][4];
#pragma unroll
    for (int mi = 0; mi < 2; mi++)
#pragma unroll
        for (int nj = 0; nj < 8; nj++)
#pragma unroll
            for (int q = 0; q < 4; q++) acc[mi][nj][q] = 0.0f;

    LOADS(0, 0, mb0);
    LOADS(1, 1, mb1);

    for (int k = 0; k < nk; k++) {
        if (!ABULK) {
            if (k + 1 < nk) cp_wait<1>();
            else            cp_wait<0>();
        }
        mbar_wait((k & 1) ? mb1 : mb0, (k >> 1) & 1);
        __syncthreads();

        const uint32_t sb = sbase + (uint32_t)(k & 1) * STAGE;
#pragma unroll
        for (int ks = 0; ks < 2; ks++) {
            uint32_t ah[2][4], al[2][4];
#pragma unroll
            for (int mi = 0; mi < 2; mi++) {
                const uint32_t ad = sb + aRow[mi]
                    + ((((uint32_t)(ks << 1) + half + aSw[mi]) & 3) << 4);
                ldmat4(ah[mi], ad + OFF_AH);
                ldmat4(al[mi], ad + OFF_AL);
            }
#pragma unroll
            for (int g = 0; g < 4; g++) {
                uint32_t bh[4], bl[4];
                const uint32_t bd = sb + bRow[g]
                    + ((((uint32_t)(ks << 1) + half + bSw[g]) & 3) << 4);
                ldmat4(bh, bd + OFF_BH);
                ldmat4(bl, bd + OFF_BL);
#pragma unroll
                for (int mi = 0; mi < 2; mi++) {
                    mma16816(acc[mi][2 * g],     ah[mi], bh[0], bh[2]);
                    mma16816(acc[mi][2 * g + 1], ah[mi], bh[1], bh[3]);
                }
#pragma unroll
                for (int mi = 0; mi < 2; mi++) {
                    mma16816(acc[mi][2 * g],     al[mi], bh[0], bh[2]);
                    mma16816(acc[mi][2 * g + 1], al[mi], bh[1], bh[3]);
                }
#pragma unroll
                for (int mi = 0; mi < 2; mi++) {
                    mma16816(acc[mi][2 * g],     ah[mi], bl[0], bl[2]);
                    mma16816(acc[mi][2 * g + 1], ah[mi], bl[1], bl[3]);
                }
            }
        }
        __syncthreads();
        if (k + 2 < nk) LOADS(k + 2, k & 1, (k & 1) ? mb1 : mb0);
    }

    // ---------- epilogue ----------
    const int er = lane >> 2, ec = (lane & 3) * 2;
#pragma unroll
    for (int mi = 0; mi < 2; mi++) {
        const int rbase = m0 + warp_m + mi * 16 + er;
#pragma unroll
        for (int nj = 0; nj < 8; nj++) {
            const int col = n0 + warp_n + nj * 8 + ec;
            const float b0 = bias[col], b1 = bias[col + 1];
            float2 v;
            v.x = acc[mi][nj][0] + b0;
            v.y = acc[mi][nj][1] + b1;
            *(float2*)&C[(size_t)rbase * Ntot + col] = v;
            v.x = acc[mi][nj][2] + b0;
            v.y = acc[mi][nj][3] + b1;
            *(float2*)&C[(size_t)(rbase + 8) * Ntot + col] = v;
        }
    }
#undef LOADS
}

// -------------------- cell / epilogue kernels -------------------------------
__device__ __forceinline__ float sigf(float x) { return 1.0f / (1.0f + expf(-x)); }

__device__ __forceinline__ void store_h(size_t ob, float hn) {
    const __nv_bfloat16 hi = __float2bfloat16(hn);
    g_hh[ob] = hi;
    g_hl[ob] = __float2bfloat16(hn - __bfloat162float(hi));
}

__global__ void cell_leaf_kernel(const float* __restrict__ buf)
{
    const size_t idx = (size_t)blockIdx.x * blockDim.x + threadIdx.x;
    if (idx >= (size_t)B_ * LVS * H_) return;
    const int n = (int)(idx & (H_ - 1));
    const size_t r = idx >> 9;
    const float* row = buf + r * TH;
    const float i_ = row[n], o_ = row[n + 512], u_ = row[n + 1024];
    const float cn = sigf(i_) * tanhf(u_);
    const float hn = sigf(o_) * tanhf(cn);
    const int b = (int)(r >> 8), leaf = (int)(r & 255);
    const size_t ob = ((size_t)b * NN + leaf) * H_ + n;
    g_c[ob] = cn;
    store_h(ob, hn);
}

__global__ void cell_level_kernel(const float* __restrict__ buf,
                                  int lm, int off, int off_prev, int total)
{
    const int idx = blockIdx.x * blockDim.x + threadIdx.x;
    if (idx >= total) return;
    const int n = idx & (H_ - 1);
    const int r = idx >> 9;
    const int b = r >> lm;
    const int j = r & ((1 << lm) - 1);
    const float* row = buf + (size_t)r * NC;
    const float i_ = row[n], o_ = row[n + 512], u_ = row[n + 1024];
    const float f0 = row[1536 + n], f1 = row[2048 + n];
    const size_t cb = ((size_t)b * NN + off_prev + 2 * j) * H_ + n;
    const float cf = sigf(f0) * g_c[cb] + sigf(f1) * g_c[cb + H_];
    const float cn = sigf(i_) * tanhf(u_) + cf;
    const float hn = sigf(o_) * tanhf(cn);
    const size_t ob = ((size_t)b * NN + off + j) * H_ + n;
    g_c[ob] = cn;
    store_h(ob, hn);
}

__global__ void classify_kernel(const float* __restrict__ lw,
                                const float* __restrict__ lb,
                                float* __restrict__ out)
{
    const int node = blockIdx.x * blockDim.x + threadIdx.x;
    if (node >= B_ * NN) return;
    const __nv_bfloat162* hh = (const __nv_bfloat162*)(g_hh + (size_t)node * H_);
    const __nv_bfloat162* hl = (const __nv_bfloat162*)(g_hl + (size_t)node * H_);
    float acc[5] = {0.f, 0.f, 0.f, 0.f, 0.f};
#pragma unroll 4
    for (int k2 = 0; k2 < 256; k2++) {
        const float2 a = __bfloat1622float2(hh[k2]);
        const float2 b = __bfloat1622float2(hl[k2]);
        const float h0 = a.x + b.x, h1 = a.y + b.y;
#pragma unroll
        for (int c = 0; c < 5; c++)
            acc[c] += h0 * lw[c * H_ + 2 * k2] + h1 * lw[c * H_ + 2 * k2 + 1];
    }
#pragma unroll
    for (int c = 0; c < 5; c++)
        out[(size_t)node * 5 + c] = acc[c] + lb[c];
}

// -------------------- packing / gather (chunked + swizzled) -----------------
__device__ __forceinline__ void split_store(float v, __nv_bfloat16* hi,
                                            __nv_bfloat16* lo, size_t half_idx) {
    const __nv_bfloat16 h = __float2bfloat16(v);
    hi[half_idx] = h;
    lo[half_idx] = __float2bfloat16(v - __bfloat162float(h));
}
__device__ __forceinline__ size_t chunk_off(int row, int k, long plane) {
    const int kc = k >> 5;
    const uint32_t g = ((uint32_t)(k & 31)) >> 3;
    const size_t byte = (size_t)kc * plane + (size_t)row * 64
                      + swz(g, (uint32_t)row) + (size_t)(k & 7) * 2;
    return byte >> 1;   // bf16 index
}

__global__ void pack_wcat_kernel(const float* __restrict__ Uiou,
                                 const float* __restrict__ Uf)
{
    const int idx = blockIdx.x * blockDim.x + threadIdx.x;
    if (idx >= NC * 1024) return;
    const int n = idx >> 10, k = idx & 1023;
    const float v = (n < TH) ? Uiou[(size_t)n * 1024 + k]
                             : Uf[(size_t)(n - TH) * 1024 + k];
    split_store(v, g_wch, g_wcl, chunk_off(n, k, PLANE_WC));
}

__global__ void pack_wleaf_kernel(const float* __restrict__ W)
{
    const int idx = blockIdx.x * blockDim.x + threadIdx.x;
    if (idx >= TH * KLF) return;
    const int n = idx / KLF, k = idx - n * KLF;
    const float v = (k < X_) ? W[(size_t)n * X_ + k] : 0.0f;
    split_store(v, g_wlh, g_wll, chunk_off(n, k, PLANE_WL));
}

__global__ void pack_bias_kernel(const float* __restrict__ bi,
                                 const float* __restrict__ bf)
{
    const int n = blockIdx.x * blockDim.x + threadIdx.x;
    if (n < NC) g_bc[n] = (n < TH) ? bi[n] : bf[n - TH];
}

__global__ void gather_x_kernel(const int* __restrict__ wid,
                                const float* __restrict__ emb)
{
    const int r = blockIdx.x;
    const int c = threadIdx.x;
    if (c >= KLF) return;
    const float v = (c < X_) ? emb[(size_t)wid[r] * X_ + c] : 0.0f;
    split_store(v, g_xh, g_xl, chunk_off(r, c, PLANE_X));
}

// -------------------- launch ------------------------------------------------
extern "C" void kernel_launch(void* const* d_in, const int* in_sizes, int n_in,
                              void* d_out, int out_size)
{
    const int*   wordid  = (const int*)  d_in[0];
    const float* emb     = (const float*)d_in[1];
    const float* W_iou_w = (const float*)d_in[2];
    const float* W_iou_b = (const float*)d_in[3];
    const float* U_iou_w = (const float*)d_in[4];
    const float* U_iou_b = (const float*)d_in[5];
    const float* U_f_w   = (const float*)d_in[6];
    const float* U_f_b   = (const float*)d_in[7];
    const float* lin_w   = (const float*)d_in[8];
    const float* lin_b   = (const float*)d_in[9];
    float* out = (float*)d_out;
    (void)in_sizes; (void)n_in; (void)out_size;

    float *pbuf, *pbc;
    __nv_bfloat16 *phh, *phl, *pxh, *pxl, *pwch, *pwcl, *pwlh, *pwll;
    cudaGetSymbolAddress((void**)&pbuf, g_buf);
    cudaGetSymbolAddress((void**)&pbc,  g_bc);
    cudaGetSymbolAddress((void**)&phh,  g_hh);
    cudaGetSymbolAddress((void**)&phl,  g_hl);
    cudaGetSymbolAddress((void**)&pxh,  g_xh);
    cudaGetSymbolAddress((void**)&pxl,  g_xl);
    cudaGetSymbolAddress((void**)&pwch, g_wch);
    cudaGetSymbolAddress((void**)&pwcl, g_wcl);
    cudaGetSymbolAddress((void**)&pwlh, g_wlh);
    cudaGetSymbolAddress((void**)&pwll, g_wll);

    cudaFuncSetAttribute(gemm_mma_kernel<false>,
                         cudaFuncAttributeMaxDynamicSharedMemorySize, SMEM_BYTES);
    cudaFuncSetAttribute(gemm_mma_kernel<true>,
                         cudaFuncAttributeMaxDynamicSharedMemorySize, SMEM_BYTES);

    // ---- prep ----
    pack_wcat_kernel <<<(NC * 1024 + 255) / 256, 256>>>(U_iou_w, U_f_w);
    pack_wleaf_kernel<<<(TH * KLF + 255) / 256, 256>>>(W_iou_w);
    pack_bias_kernel <<<(NC + 255) / 256, 256>>>(U_iou_b, U_f_b);
    gather_x_kernel  <<<B_ * LVS, KLF>>>(wordid, emb);

    // ---- leaves: all-bulk GEMM ----
    {
        dim3 g(TH / BN, (B_ * LVS) / BM);   // 12 x 512
        gemm_mma_kernel<true><<<g, 256, SMEM_BYTES>>>(
            pxh, pxl, pwlh, pwll, W_iou_b, pbuf,
            TH, PLANE_WL, PLANE_X, KLF / BK, 0, 0);
        cell_leaf_kernel<<<(B_ * LVS * H_) / 256, 256>>>(pbuf);
    }

    // ---- internal levels: bulk-B, LDGSTS-A GEMM ----
    static const int offs[10] = {0, 256, 384, 448, 480, 496, 504, 508, 510, 511};
    for (int l = 1; l <= 8; l++) {
        const int m = LVS >> l;
        const int M = B_ * m;
        const int lm = 8 - l;
        dim3 g(NC / BN, M / BM);            // 20 x (M/128)
        gemm_mma_kernel<false><<<g, 256, SMEM_BYTES>>>(
            phh, phl, pwch, pwcl, pbc, pbuf,
            NC, PLANE_WC, 0, 1024 / BK, lm, offs[l - 1]);
        const int total = M * H_;
        cell_level_kernel<<<(total + 255) / 256, 256>>>(pbuf, lm, offs[l],
                                                        offs[l - 1], total);
    }

    // ---- classifier ----
    classify_kernel<<<(B_ * NN + 127) / 128, 128>>>(lin_w, lin_b, out);
}